// round 10
// baseline (speedup 1.0000x reference)
#include <cuda_runtime.h>
#include <math_constants.h>

#define IMG    256
#define DET    362          // int(256*sqrt(2)+0.5)
#define A_FULL 177          // (45-1)*4 + 1
#define N_ACQ  45
#define NB     2

// Padded image geometry: 2-cell zero border (coords reach index -2..256)
#define PW     264          // padded row stride in float4 quads
#define PH     260
#define POFF   (2 * PW + 2)

// radon warp tiling: 8 t-bins x 4 k-samples per warp
#define TPB    256          // 8 warps -> 64 t-bins per block
#define TTILES 6            // ceil(362/64)

// bp chunking
#define NCHBP  4
#define ABP    45           // ceil(177/4)
#define NPAIR  (NB * IMG * IMG / 2)   // 65536 pixel pairs

// Scratch (allocation-free)
__device__ float  g_sino[NB * A_FULL * DET];   // radon output
__device__ float2 g_sf2 [NB * A_FULL * DET];   // filtered sinogram, pair-packed
__device__ float4 g_imQ  [NB * PH * PW];       // quad-packed padded image
__device__ float4 g_imTQ [NB * PH * PW];       // quad-packed padded transposed image
__device__ float2 g_bp2 [NCHBP * NPAIR];       // bp partials, pixel-pair packed

// ---------------------------------------------------------------------------
// Kernel 0: build quad-packed padded images.
// imQ [r][c] = (I[r][c],  I[r][c+1],  I[r+1][c],  I[r+1][c+1])
// imTQ[r][c] = (I[c][r],  I[c+1][r],  I[c][r+1],  I[c+1][r+1])
// ---------------------------------------------------------------------------
__global__ void prep_kernel(const float* __restrict__ img)
{
    const int i = blockIdx.x * blockDim.x + threadIdx.x;
    if (i >= NB * PH * PW) return;
    const int b   = i / (PH * PW);
    const int rem = i - b * (PH * PW);
    const int r   = rem / PW - 2;
    const int c   = rem - (r + 2) * PW - 2;
    const float* im = img + b * IMG * IMG;

    const bool rv0 = ((unsigned)r       < IMG);
    const bool rv1 = ((unsigned)(r + 1) < IMG);
    const bool cv0 = ((unsigned)c       < IMG);
    const bool cv1 = ((unsigned)(c + 1) < IMG);

    float4 v, vt;
    v.x  = (rv0 && cv0) ? __ldg(im + r * IMG + c)             : 0.f;
    v.y  = (rv0 && cv1) ? __ldg(im + r * IMG + c + 1)         : 0.f;
    v.z  = (rv1 && cv0) ? __ldg(im + (r + 1) * IMG + c)       : 0.f;
    v.w  = (rv1 && cv1) ? __ldg(im + (r + 1) * IMG + c + 1)   : 0.f;
    vt.x = (cv0 && rv0) ? __ldg(im + c * IMG + r)             : 0.f;
    vt.y = (cv1 && rv0) ? __ldg(im + (c + 1) * IMG + r)       : 0.f;
    vt.z = (cv0 && rv1) ? __ldg(im + c * IMG + r + 1)         : 0.f;
    vt.w = (cv1 && rv1) ? __ldg(im + (c + 1) * IMG + r + 1)   : 0.f;
    g_imQ [i] = v;
    g_imTQ[i] = vt;
}

// ---------------------------------------------------------------------------
// Kernel 1: Radon transform. grid = (A_FULL, NB, TTILES), block = 256.
// Warp = 8 t-bins x 4 k-strides; one LDG.128 per bilinear sample.
// ---------------------------------------------------------------------------
__global__ void radon_kernel(const float* __restrict__ thetas_deg)
{
    const int a    = blockIdx.x;
    const int b    = blockIdx.y;
    const int w    = threadIdx.x >> 5;
    const int lane = threadIdx.x & 31;
    const int tt   = lane & 7;
    const int kk   = lane >> 3;
    const int t    = blockIdx.z * 64 + w * 8 + tt;

    const float th = thetas_deg[a] * (float)(CUDART_PI / 180.0);
    const float c  = cosf(th);
    const float s  = sinf(th);

    const bool swp = (s > fabsf(c));
    const float4* imc = (swp ? g_imTQ : g_imQ) + b * PH * PW + POFF;

    float q0 = 0.f, r0 = 0.f, dq = 0.f, dr = 0.f;
    int klo = DET, khi = 0;
    if (t < DET) {
        const float T  = (float)t - (float)(DET - 1) * 0.5f;
        const float bx = T * c + 127.5f;
        const float by = T * s + 127.5f;
        if (swp) { q0 = by; r0 = bx; dq =  c; dr = -s; }
        else     { q0 = bx; r0 = by; dq = -s; dr =  c; }

        float Slo = -1e9f, Shi = 1e9f;
        if (dq > 1e-6f)       { Slo = fmaxf(Slo, (-1.f - q0) / dq); Shi = fminf(Shi, (256.f - q0) / dq); }
        else if (dq < -1e-6f) { Slo = fmaxf(Slo, (256.f - q0) / dq); Shi = fminf(Shi, (-1.f - q0) / dq); }
        else if (q0 <= -1.f || q0 >= 256.f) Shi = -2e9f;
        if (dr > 1e-6f)       { Slo = fmaxf(Slo, (-1.f - r0) / dr); Shi = fminf(Shi, (256.f - r0) / dr); }
        else if (dr < -1e-6f) { Slo = fmaxf(Slo, (256.f - r0) / dr); Shi = fminf(Shi, (-1.f - r0) / dr); }
        else if (r0 <= -1.f || r0 >= 256.f) Shi = -2e9f;

        const float HALF = (float)(DET - 1) * 0.5f;
        klo = (int)floorf(Slo + HALF);
        khi = (int)ceilf (Shi + HALF) + 1;
        klo = max(klo, 0);
        khi = min(khi, DET);
        if (khi < klo) { klo = DET; khi = 0; }
    }

    const int kmin = __reduce_min_sync(0xffffffffu, klo);
    const int kmax = __reduce_max_sync(0xffffffffu, khi);

    const float HALF = (float)(DET - 1) * 0.5f;
    float acc = 0.f;
    for (int k = kmin + kk; k < kmax; k += 4) {
        if (k >= klo && k < khi) {
            const float S  = (float)k - HALF;
            const float qs = fmaf(S, dq, q0);
            const float rs = fmaf(S, dr, r0);
            const float qf = floorf(qs), rf = floorf(rs);
            const float wq = qs - qf,    wr = rs - rf;
            const int   qi = (int)qf,    ri = (int)rf;

            const float4 v = __ldg(imc + ri * PW + qi);  // (v00,v01,v10,v11)
            const float top = fmaf(wq, v.y - v.x, v.x);
            const float bot = fmaf(wq, v.w - v.z, v.z);
            acc = fmaf(wr, bot - top, acc + top);
        }
    }

    acc += __shfl_xor_sync(0xffffffffu, acc, 8);
    acc += __shfl_xor_sync(0xffffffffu, acc, 16);

    if (kk == 0 && t < DET)
        g_sino[(b * A_FULL + a) * DET + t] = acc;
}

// ---------------------------------------------------------------------------
// Kernel 2: data-consistency + exact ramp-filter conv, pair-packed output.
//   h[0]=0.5, h[m odd]=-2/(pi m)^2, h[m even>0]=0 (exactly the FFT filter)
// 4 independent accumulators break the serial FADD dependency chain.
// ---------------------------------------------------------------------------
__global__ void filter_kernel(const float* __restrict__ s_target)
{
    __shared__ float xcol[DET];
    __shared__ float wtab[DET];
    __shared__ float res [DET];

    const int a = blockIdx.x;
    const int b = blockIdx.y;
    const int d = threadIdx.x;

    for (int i = threadIdx.x; i < DET; i += blockDim.x) {
        float x = g_sino[(b * A_FULL + a) * DET + i];
        if ((a & 3) == 0) {
            const int j = a >> 2;
            x = __ldg(s_target + (b * DET + i) * N_ACQ + j) - x;
        }
        xcol[i] = x;

        float wm;
        if (i == 0)      wm = 0.5f;
        else if (i & 1)  { const float fm = (float)i * (float)CUDART_PI; wm = -2.0f / (fm * fm); }
        else             wm = 0.f;
        wtab[i] = wm;
    }
    __syncthreads();

    if (d < DET) {
        const int k0 = (d & 1) ^ 1;           // opposite parity -> |d-k| odd
        float a0 = 0.f, a1 = 0.f, a2 = 0.f, a3 = 0.f;
        int k = k0;
        for (; k + 6 < DET; k += 8) {
            a0 = fmaf(wtab[abs(d - k)],       xcol[k],     a0);
            a1 = fmaf(wtab[abs(d - (k + 2))], xcol[k + 2], a1);
            a2 = fmaf(wtab[abs(d - (k + 4))], xcol[k + 4], a2);
            a3 = fmaf(wtab[abs(d - (k + 6))], xcol[k + 6], a3);
        }
        for (; k < DET; k += 2)
            a0 = fmaf(wtab[abs(d - k)], xcol[k], a0);
        res[d] = 0.5f * xcol[d] + ((a0 + a1) + (a2 + a3));
    }
    __syncthreads();

    if (d < DET) {
        float2 o;
        o.x = res[d];
        o.y = (d + 1 < DET) ? res[d + 1] : 0.f;
        g_sf2[(b * A_FULL + a) * DET + d] = o;
    }
}

// ---------------------------------------------------------------------------
// Kernel 3: Filtered backprojection. 2x2 pixel tile per thread:
// t01 = t00+cs, t10 = t00+sn, t11 = t01+sn -> 4 independent chains (MLP=4),
// one loop's control/addressing amortized over 4 samples.
// grid = (128, NCHBP), block = 256. 512 blocks total.
// ---------------------------------------------------------------------------
__global__ void bp_kernel(const float* __restrict__ thetas_deg)
{
    __shared__ float cs[ABP];
    __shared__ float sn[ABP];

    const int ch  = blockIdx.y;
    const int a0  = ch * ABP;
    const int na  = min(A_FULL - a0, ABP);

    if (threadIdx.x < na) {
        const float th = thetas_deg[a0 + threadIdx.x] * (float)(CUDART_PI / 180.0);
        cs[threadIdx.x] = cosf(th);
        sn[threadIdx.x] = sinf(th);
    }
    __syncthreads();

    const int p   = blockIdx.x * blockDim.x + threadIdx.x;  // 0..32767 tile id
    const int b   = p >> 14;             // 2 batches x 128 ypairs x 128 xpairs
    const int rem = p & 16383;
    const int yp  = rem >> 7;
    const int xp  = rem & 127;
    const int y0  = yp << 1;
    const int x0  = xp << 1;

    const float gx = (float)x0 - 127.5f;
    const float gy = (float)y0 - 127.5f;

    const float2* __restrict__ sfb = g_sf2 + (b * A_FULL + a0) * DET;

    float acc00 = 0.f, acc01 = 0.f, acc10 = 0.f, acc11 = 0.f;
    #pragma unroll 5
    for (int a = 0; a < na; a++) {
        const float cc = cs[a], ss = sn[a];
        const float t00 = fmaf(cc, gx, fmaf(ss, gy, (float)(DET - 1) * 0.5f));
        const float t01 = t00 + cc;
        const float t10 = t00 + ss;
        const float t11 = t01 + ss;
        const int i00 = (int)t00, i01 = (int)t01, i10 = (int)t10, i11 = (int)t11;
        const float w00 = t00 - (float)i00;
        const float w01 = t01 - (float)i01;
        const float w10 = t10 - (float)i10;
        const float w11 = t11 - (float)i11;
        const float2* row = sfb + a * DET;
        const float2 v00 = __ldg(row + i00);
        const float2 v01 = __ldg(row + i01);
        const float2 v10 = __ldg(row + i10);
        const float2 v11 = __ldg(row + i11);
        acc00 = fmaf(w00, v00.y - v00.x, acc00 + v00.x);
        acc01 = fmaf(w01, v01.y - v01.x, acc01 + v01.x);
        acc10 = fmaf(w10, v10.y - v10.x, acc10 + v10.x);
        acc11 = fmaf(w11, v11.y - v11.x, acc11 + v11.x);
    }

    // pixel-pair ids: row y0 and y0+1
    const int pairBase = b * 32768 + y0 * 128 + xp;
    float2 o0; o0.x = acc00; o0.y = acc01;
    float2 o1; o1.x = acc10; o1.y = acc11;
    g_bp2[ch * NPAIR + pairBase]        = o0;
    g_bp2[ch * NPAIR + pairBase + 128]  = o1;
}

// ---------------------------------------------------------------------------
// Kernel 4: reduce bp partials + scale (pair-packed).
// ---------------------------------------------------------------------------
__global__ void bp_reduce_kernel(float2* __restrict__ out)
{
    const int p = blockIdx.x * blockDim.x + threadIdx.x;
    if (p >= NPAIR) return;
    float ax = 0.f, ay = 0.f;
    #pragma unroll
    for (int ci = 0; ci < NCHBP; ci++) {
        const float2 v = g_bp2[ci * NPAIR + p];
        ax += v.x; ay += v.y;
    }
    const float sc = (float)(CUDART_PI / (2.0 * A_FULL));
    float2 o; o.x = ax * sc; o.y = ay * sc;
    out[p] = o;
}

// ---------------------------------------------------------------------------
extern "C" void kernel_launch(void* const* d_in, const int* in_sizes, int n_in,
                              void* d_out, int out_size)
{
    const float* x_source = nullptr;
    const float* s_target = nullptr;
    const float* thetas   = nullptr;
    for (int i = 0; i < n_in; i++) {
        if      (in_sizes[i] == NB * IMG * IMG)   x_source = (const float*)d_in[i];
        else if (in_sizes[i] == NB * DET * N_ACQ) s_target = (const float*)d_in[i];
        else if (in_sizes[i] == A_FULL)           thetas   = (const float*)d_in[i];
    }

    prep_kernel     <<<(NB * PH * PW + 255) / 256, 256>>>(x_source);
    radon_kernel    <<<dim3(A_FULL, NB, TTILES), TPB>>>(thetas);
    filter_kernel   <<<dim3(A_FULL, NB), 384>>>(s_target);
    bp_kernel       <<<dim3(128, NCHBP), 256>>>(thetas);
    bp_reduce_kernel<<<256, 256>>>((float2*)d_out);
}

// round 11
// speedup vs baseline: 1.0575x; 1.0575x over previous
#include <cuda_runtime.h>
#include <math_constants.h>

#define IMG    256
#define DET    362          // int(256*sqrt(2)+0.5)
#define A_FULL 177          // (45-1)*4 + 1
#define N_ACQ  45
#define NB     2

// Padded image geometry: 2-cell zero border (coords reach index -2..256)
#define PW     264          // padded row stride in float4 quads
#define PH     260
#define POFF   (2 * PW + 2)

// radon warp tiling: 8 t-bins x 4 k-samples per warp
#define TPB    256          // 8 warps -> 64 t-bins per block
#define TTILES 6            // ceil(362/64)

// bp chunking: 8 angle chunks of 23 -> grid 1024 blocks at ILP=4
#define NCHBP  8
#define ABP    23           // ceil(177/8)
#define NPAIR  (NB * IMG * IMG / 2)   // 65536 pixel pairs

// Scratch (allocation-free)
__device__ float  g_sino[NB * A_FULL * DET];   // radon output
__device__ float2 g_sf2 [NB * A_FULL * DET];   // filtered sinogram, pair-packed
__device__ float4 g_imQ  [NB * PH * PW];       // quad-packed padded image
__device__ float4 g_imTQ [NB * PH * PW];       // quad-packed padded transposed image
__device__ float2 g_bp2 [NCHBP * NPAIR];       // bp partials, pixel-pair packed

// ---------------------------------------------------------------------------
// Kernel 0: build quad-packed padded images.
// imQ [r][c] = (I[r][c],  I[r][c+1],  I[r+1][c],  I[r+1][c+1])
// imTQ[r][c] = (I[c][r],  I[c+1][r],  I[c][r+1],  I[c+1][r+1])
// ---------------------------------------------------------------------------
__global__ void prep_kernel(const float* __restrict__ img)
{
    const int i = blockIdx.x * blockDim.x + threadIdx.x;
    if (i >= NB * PH * PW) return;
    const int b   = i / (PH * PW);
    const int rem = i - b * (PH * PW);
    const int r   = rem / PW - 2;
    const int c   = rem - (r + 2) * PW - 2;
    const float* im = img + b * IMG * IMG;

    const bool rv0 = ((unsigned)r       < IMG);
    const bool rv1 = ((unsigned)(r + 1) < IMG);
    const bool cv0 = ((unsigned)c       < IMG);
    const bool cv1 = ((unsigned)(c + 1) < IMG);

    float4 v, vt;
    v.x  = (rv0 && cv0) ? __ldg(im + r * IMG + c)             : 0.f;
    v.y  = (rv0 && cv1) ? __ldg(im + r * IMG + c + 1)         : 0.f;
    v.z  = (rv1 && cv0) ? __ldg(im + (r + 1) * IMG + c)       : 0.f;
    v.w  = (rv1 && cv1) ? __ldg(im + (r + 1) * IMG + c + 1)   : 0.f;
    vt.x = (cv0 && rv0) ? __ldg(im + c * IMG + r)             : 0.f;
    vt.y = (cv1 && rv0) ? __ldg(im + (c + 1) * IMG + r)       : 0.f;
    vt.z = (cv0 && rv1) ? __ldg(im + c * IMG + r + 1)         : 0.f;
    vt.w = (cv1 && rv1) ? __ldg(im + (c + 1) * IMG + r + 1)   : 0.f;
    g_imQ [i] = v;
    g_imTQ[i] = vt;
}

// ---------------------------------------------------------------------------
// Kernel 1: Radon transform. grid = (A_FULL, NB, TTILES), block = 256.
// Warp = 8 t-bins x 4 k-strides; one LDG.128 per bilinear sample.
// ---------------------------------------------------------------------------
__global__ void radon_kernel(const float* __restrict__ thetas_deg)
{
    const int a    = blockIdx.x;
    const int b    = blockIdx.y;
    const int w    = threadIdx.x >> 5;
    const int lane = threadIdx.x & 31;
    const int tt   = lane & 7;
    const int kk   = lane >> 3;
    const int t    = blockIdx.z * 64 + w * 8 + tt;

    const float th = thetas_deg[a] * (float)(CUDART_PI / 180.0);
    const float c  = cosf(th);
    const float s  = sinf(th);

    const bool swp = (s > fabsf(c));
    const float4* imc = (swp ? g_imTQ : g_imQ) + b * PH * PW + POFF;

    float q0 = 0.f, r0 = 0.f, dq = 0.f, dr = 0.f;
    int klo = DET, khi = 0;
    if (t < DET) {
        const float T  = (float)t - (float)(DET - 1) * 0.5f;
        const float bx = T * c + 127.5f;
        const float by = T * s + 127.5f;
        if (swp) { q0 = by; r0 = bx; dq =  c; dr = -s; }
        else     { q0 = bx; r0 = by; dq = -s; dr =  c; }

        float Slo = -1e9f, Shi = 1e9f;
        if (dq > 1e-6f)       { Slo = fmaxf(Slo, (-1.f - q0) / dq); Shi = fminf(Shi, (256.f - q0) / dq); }
        else if (dq < -1e-6f) { Slo = fmaxf(Slo, (256.f - q0) / dq); Shi = fminf(Shi, (-1.f - q0) / dq); }
        else if (q0 <= -1.f || q0 >= 256.f) Shi = -2e9f;
        if (dr > 1e-6f)       { Slo = fmaxf(Slo, (-1.f - r0) / dr); Shi = fminf(Shi, (256.f - r0) / dr); }
        else if (dr < -1e-6f) { Slo = fmaxf(Slo, (256.f - r0) / dr); Shi = fminf(Shi, (-1.f - r0) / dr); }
        else if (r0 <= -1.f || r0 >= 256.f) Shi = -2e9f;

        const float HALF = (float)(DET - 1) * 0.5f;
        klo = (int)floorf(Slo + HALF);
        khi = (int)ceilf (Shi + HALF) + 1;
        klo = max(klo, 0);
        khi = min(khi, DET);
        if (khi < klo) { klo = DET; khi = 0; }
    }

    const int kmin = __reduce_min_sync(0xffffffffu, klo);
    const int kmax = __reduce_max_sync(0xffffffffu, khi);

    const float HALF = (float)(DET - 1) * 0.5f;
    float acc = 0.f;
    for (int k = kmin + kk; k < kmax; k += 4) {
        if (k >= klo && k < khi) {
            const float S  = (float)k - HALF;
            const float qs = fmaf(S, dq, q0);
            const float rs = fmaf(S, dr, r0);
            const float qf = floorf(qs), rf = floorf(rs);
            const float wq = qs - qf,    wr = rs - rf;
            const int   qi = (int)qf,    ri = (int)rf;

            const float4 v = __ldg(imc + ri * PW + qi);  // (v00,v01,v10,v11)
            const float top = fmaf(wq, v.y - v.x, v.x);
            const float bot = fmaf(wq, v.w - v.z, v.z);
            acc = fmaf(wr, bot - top, acc + top);
        }
    }

    acc += __shfl_xor_sync(0xffffffffu, acc, 8);
    acc += __shfl_xor_sync(0xffffffffu, acc, 16);

    if (kk == 0 && t < DET)
        g_sino[(b * A_FULL + a) * DET + t] = acc;
}

// ---------------------------------------------------------------------------
// Kernel 2: data-consistency + exact ramp-filter conv, pair-packed output.
//   h[0]=0.5, h[m odd]=-2/(pi m)^2, h[m even>0]=0 (exactly the FFT filter)
// 4 independent accumulators break the serial FADD dependency chain.
// ---------------------------------------------------------------------------
__global__ void filter_kernel(const float* __restrict__ s_target)
{
    __shared__ float xcol[DET];
    __shared__ float wtab[DET];
    __shared__ float res [DET];

    const int a = blockIdx.x;
    const int b = blockIdx.y;
    const int d = threadIdx.x;

    for (int i = threadIdx.x; i < DET; i += blockDim.x) {
        float x = g_sino[(b * A_FULL + a) * DET + i];
        if ((a & 3) == 0) {
            const int j = a >> 2;
            x = __ldg(s_target + (b * DET + i) * N_ACQ + j) - x;
        }
        xcol[i] = x;

        float wm;
        if (i == 0)      wm = 0.5f;
        else if (i & 1)  { const float fm = (float)i * (float)CUDART_PI; wm = -2.0f / (fm * fm); }
        else             wm = 0.f;
        wtab[i] = wm;
    }
    __syncthreads();

    if (d < DET) {
        const int k0 = (d & 1) ^ 1;           // opposite parity -> |d-k| odd
        float a0 = 0.f, a1 = 0.f, a2 = 0.f, a3 = 0.f;
        int k = k0;
        for (; k + 6 < DET; k += 8) {
            a0 = fmaf(wtab[abs(d - k)],       xcol[k],     a0);
            a1 = fmaf(wtab[abs(d - (k + 2))], xcol[k + 2], a1);
            a2 = fmaf(wtab[abs(d - (k + 4))], xcol[k + 4], a2);
            a3 = fmaf(wtab[abs(d - (k + 6))], xcol[k + 6], a3);
        }
        for (; k < DET; k += 2)
            a0 = fmaf(wtab[abs(d - k)], xcol[k], a0);
        res[d] = 0.5f * xcol[d] + ((a0 + a1) + (a2 + a3));
    }
    __syncthreads();

    if (d < DET) {
        float2 o;
        o.x = res[d];
        o.y = (d + 1 < DET) ? res[d + 1] : 0.f;
        g_sf2[(b * A_FULL + a) * DET + d] = o;
    }
}

// ---------------------------------------------------------------------------
// Kernel 3: Filtered backprojection. 2x2 pixel tile per thread (ILP=4),
// 8 angle chunks -> grid (128, 8) = 1024 blocks: full occupancy AND MLP=4.
// ---------------------------------------------------------------------------
__global__ void bp_kernel(const float* __restrict__ thetas_deg)
{
    __shared__ float cs[ABP];
    __shared__ float sn[ABP];

    const int ch  = blockIdx.y;
    const int a0  = ch * ABP;
    const int na  = min(A_FULL - a0, ABP);

    if (threadIdx.x < na) {
        const float th = thetas_deg[a0 + threadIdx.x] * (float)(CUDART_PI / 180.0);
        cs[threadIdx.x] = cosf(th);
        sn[threadIdx.x] = sinf(th);
    }
    __syncthreads();

    const int p   = blockIdx.x * blockDim.x + threadIdx.x;  // 0..32767 tile id
    const int b   = p >> 14;             // 2 batches x 128 ypairs x 128 xpairs
    const int rem = p & 16383;
    const int yp  = rem >> 7;
    const int xp  = rem & 127;
    const int y0  = yp << 1;
    const int x0  = xp << 1;

    const float gx = (float)x0 - 127.5f;
    const float gy = (float)y0 - 127.5f;

    const float2* __restrict__ sfb = g_sf2 + (b * A_FULL + a0) * DET;

    float acc00 = 0.f, acc01 = 0.f, acc10 = 0.f, acc11 = 0.f;
    #pragma unroll
    for (int a = 0; a < ABP; a++) {
        if (a >= na) break;
        const float cc = cs[a], ss = sn[a];
        const float t00 = fmaf(cc, gx, fmaf(ss, gy, (float)(DET - 1) * 0.5f));
        const float t01 = t00 + cc;
        const float t10 = t00 + ss;
        const float t11 = t01 + ss;
        const int i00 = (int)t00, i01 = (int)t01, i10 = (int)t10, i11 = (int)t11;
        const float w00 = t00 - (float)i00;
        const float w01 = t01 - (float)i01;
        const float w10 = t10 - (float)i10;
        const float w11 = t11 - (float)i11;
        const float2* row = sfb + a * DET;
        const float2 v00 = __ldg(row + i00);
        const float2 v01 = __ldg(row + i01);
        const float2 v10 = __ldg(row + i10);
        const float2 v11 = __ldg(row + i11);
        acc00 = fmaf(w00, v00.y - v00.x, acc00 + v00.x);
        acc01 = fmaf(w01, v01.y - v01.x, acc01 + v01.x);
        acc10 = fmaf(w10, v10.y - v10.x, acc10 + v10.x);
        acc11 = fmaf(w11, v11.y - v11.x, acc11 + v11.x);
    }

    // pixel-pair ids: row y0 and y0+1
    const int pairBase = b * 32768 + y0 * 128 + xp;
    float2 o0; o0.x = acc00; o0.y = acc01;
    float2 o1; o1.x = acc10; o1.y = acc11;
    g_bp2[ch * NPAIR + pairBase]        = o0;
    g_bp2[ch * NPAIR + pairBase + 128]  = o1;
}

// ---------------------------------------------------------------------------
// Kernel 4: reduce bp partials + scale (pair-packed).
// ---------------------------------------------------------------------------
__global__ void bp_reduce_kernel(float2* __restrict__ out)
{
    const int p = blockIdx.x * blockDim.x + threadIdx.x;
    if (p >= NPAIR) return;
    float ax = 0.f, ay = 0.f;
    #pragma unroll
    for (int ci = 0; ci < NCHBP; ci++) {
        const float2 v = g_bp2[ci * NPAIR + p];
        ax += v.x; ay += v.y;
    }
    const float sc = (float)(CUDART_PI / (2.0 * A_FULL));
    float2 o; o.x = ax * sc; o.y = ay * sc;
    out[p] = o;
}

// ---------------------------------------------------------------------------
extern "C" void kernel_launch(void* const* d_in, const int* in_sizes, int n_in,
                              void* d_out, int out_size)
{
    const float* x_source = nullptr;
    const float* s_target = nullptr;
    const float* thetas   = nullptr;
    for (int i = 0; i < n_in; i++) {
        if      (in_sizes[i] == NB * IMG * IMG)   x_source = (const float*)d_in[i];
        else if (in_sizes[i] == NB * DET * N_ACQ) s_target = (const float*)d_in[i];
        else if (in_sizes[i] == A_FULL)           thetas   = (const float*)d_in[i];
    }

    prep_kernel     <<<(NB * PH * PW + 255) / 256, 256>>>(x_source);
    radon_kernel    <<<dim3(A_FULL, NB, TTILES), TPB>>>(thetas);
    filter_kernel   <<<dim3(A_FULL, NB), 384>>>(s_target);
    bp_kernel       <<<dim3(128, NCHBP), 256>>>(thetas);
    bp_reduce_kernel<<<256, 256>>>((float2*)d_out);
}